// round 2
// baseline (speedup 1.0000x reference)
#include <cuda_runtime.h>

#define BSZ 4
#define D 16
#define MDIM 32
#define LTOT 81

#define ADD4(a, v) do { (a).x += (v).x; (a).y += (v).y; (a).z += (v).z; (a).w += (v).w; } while (0)

// Scratch: Q2[b][p1][h][j2][jj][m] as float4 (m4 = m/4). 442 KB.
__device__ float4 g_Q2[BSZ * D * 2 * 3 * 9 * 8];

// ---------------------------------------------------------------------------
// Pass 1: block (b, p1, h) streams arr[b,p1, h*8 .. h*8+7, :, :, :] (256 KB)
// with float4 loads, contracts p3 (registers), p4 and p2 (shared) into
// Q2[b,p1,h,j2,jj,m]  where jj = j3*3 + j4.
// Position weight: p contributes to class (p-1)%3 (if p>=1) and p%3 (if p<=14).
// ---------------------------------------------------------------------------
__global__ void __launch_bounds__(1024) pass1_kernel(const float4* __restrict__ arr) {
    __shared__ float4 S[8][16][8];   // [p2l][p4][m4]  16 KB
    __shared__ float4 T[8][3][8];    // [p2l][j4][m4]   3 KB

    const int b   = blockIdx.z;
    const int p1  = blockIdx.y;
    const int h   = blockIdx.x;          // 0..1
    const int t   = threadIdx.x;
    const int m4  = t & 7;
    const int p4  = (t >> 3) & 15;
    const int p2l = t >> 7;              // 0..7
    const int p2  = h * 8 + p2l;

    const float4* __restrict__ src =
        arr + (size_t)(((((b * D + p1) * D + p2) * D) * D) + p4) * 8 + m4;

    float4 a0 = {0.f,0.f,0.f,0.f}, a1 = a0, a2 = a0;
#pragma unroll
    for (int p3 = 0; p3 < 16; ++p3) {
        float4 v = src[p3 * D * 8];
        if (p3 >= 1) {
            const int ja = (p3 - 1) % 3;
            if (ja == 0) ADD4(a0, v); else if (ja == 1) ADD4(a1, v); else ADD4(a2, v);
        }
        if (p3 <= 14) {
            const int jb = p3 % 3;
            if (jb == 0) ADD4(a0, v); else if (jb == 1) ADD4(a1, v); else ADD4(a2, v);
        }
    }

#pragma unroll
    for (int j3 = 0; j3 < 3; ++j3) {
        S[p2l][p4][m4] = (j3 == 0) ? a0 : ((j3 == 1) ? a1 : a2);
        __syncthreads();

        if (t < 192) {   // t = pp*24 + j4*8 + mm : reduce p4 -> j4 classes
            const int mm = t & 7;
            const int j4 = (t >> 3) % 3;
            const int pp = t / 24;
            float4 s = {0.f,0.f,0.f,0.f};
#pragma unroll
            for (int i = 0; i < 10; ++i) {
                const int p = 3 * (i >> 1) + j4 + (i & 1);
                ADD4(s, S[pp][p][mm]);
            }
            T[pp][j4][mm] = s;
        }
        __syncthreads();

        if (t < 72) {    // t = j2*24 + j4*8 + mm : reduce p2l -> j2 classes
            const int mm = t & 7;
            const int j4 = (t >> 3) % 3;
            const int j2 = t / 24;
            float4 s = {0.f,0.f,0.f,0.f};
#pragma unroll
            for (int pl = 0; pl < 8; ++pl) {
                const int pg = h * 8 + pl;
                const bool w = (pg >= 1 && (pg - 1) % 3 == j2) ||
                               (pg <= 14 && pg % 3 == j2);
                if (w) ADD4(s, T[pl][j4][mm]);
            }
            const int jj = j3 * 3 + j4;
            g_Q2[((((b * D + p1) * 2 + h) * 3 + j2) * 9 + jj) * 8 + mm] = s;
        }
        __syncthreads();
    }
}

// ---------------------------------------------------------------------------
// Pass 2 (fused): per-b block.
//   E[c,m]  = sum_n Bbasis[c,n] * M[n,m]                        (shared)
//   G[c,m]  = sum_{p1 in P(j1)} sum_h Q2[b,p1,h,j2,jj,m]        (20 L2 loads)
//   H[c]    = sum_m E[c,m]*G[c,m]
//   out[b,n]= K * sum_c H[c]*Acoeff[n,c],  K = 1/(16*15^4)
// ---------------------------------------------------------------------------
__global__ void __launch_bounds__(1024) pass2_kernel(const float* __restrict__ Mmat,
                                                     const float* __restrict__ Acoeff,
                                                     const float* __restrict__ Bbasis,
                                                     float* __restrict__ out) {
    __shared__ float E[LTOT * MDIM];   // 10.4 KB
    __shared__ float Hs[LTOT];

    const int b = blockIdx.x;
    const int t = threadIdx.x;

    for (int i = t; i < LTOT * MDIM; i += 1024) {
        const int c = i >> 5, m = i & 31;
        float e = 0.f;
#pragma unroll
        for (int n = 0; n < MDIM; ++n)
            e += Bbasis[c * MDIM + n] * Mmat[n * MDIM + m];
        E[i] = e;
    }
    __syncthreads();

    const int w = t >> 5, lane = t & 31;
    const float* __restrict__ q = (const float*)g_Q2;
    for (int c = w; c < LTOT; c += 32) {
        const int j4 = c % 3, j3 = (c / 3) % 3, j2 = (c / 9) % 3, j1 = c / 27;
        const int jj = j3 * 3 + j4;
        float G = 0.f;
#pragma unroll
        for (int i = 0; i < 10; ++i) {
            const int p1 = 3 * (i >> 1) + j1 + (i & 1);
            const int base = (((b * D + p1) * 2) * 3 + j2) * 9 + jj;
            G += q[base * MDIM + lane];                 // h = 0
            G += q[(base + 27) * MDIM + lane];          // h = 1
        }
        float hv = E[c * MDIM + lane] * G;
#pragma unroll
        for (int o = 16; o; o >>= 1)
            hv += __shfl_xor_sync(0xffffffffu, hv, o);
        if (lane == 0) Hs[c] = hv;
    }
    __syncthreads();

    if (t < MDIM) {
        const float K = 1.0f / (16.0f * 50625.0f);
        float s = 0.f;
#pragma unroll
        for (int c = 0; c < LTOT; ++c)
            s += Hs[c] * Acoeff[t * LTOT + c];
        out[b * MDIM + t] = s * K;
    }
}

extern "C" void kernel_launch(void* const* d_in, const int* in_sizes, int n_in,
                              void* d_out, int out_size) {
    const float4* arr   = (const float4*)d_in[0];  // [4,16,16,16,16,32]
    const float* Mmat   = (const float*)d_in[1];   // [32,32]
    const float* Acoeff = (const float*)d_in[2];   // [32,81]
    const float* Bbasis = (const float*)d_in[3];   // [81,32]
    float* out = (float*)d_out;                    // [4,32]

    dim3 g1(2, D, BSZ);                 // (h, p1, b) = 128 blocks
    pass1_kernel<<<g1, 1024>>>(arr);

    pass2_kernel<<<BSZ, 1024>>>(Mmat, Acoeff, Bbasis, out);
}

// round 3
// speedup vs baseline: 1.1345x; 1.1345x over previous
#include <cuda_runtime.h>

#define BSZ 4
#define D 16
#define MDIM 32
#define LTOT 81

#define ADD4(a, v) do { (a).x += (v).x; (a).y += (v).y; (a).z += (v).z; (a).w += (v).w; } while (0)

// Scratch: Q2[b][p1][h][j2][jj][m] as float4 (m4 = m/4). 442 KB.
__device__ float4 g_Q2[BSZ * D * 2 * 3 * 9 * 8];
__device__ float g_H[BSZ * LTOT];
__device__ unsigned int g_count = 0;

// ---------------------------------------------------------------------------
// Pass 1: block (b, p1, h) streams arr[b,p1, h*8 .. h*8+7, :, :, :] (256 KB)
// with float4 loads, contracts p3 (registers), p4 and p2 (shared) into
// Q2[b,p1,h,j2,jj,m], jj = j3*3 + j4.
// Position weight: p contributes to class (p-1)%3 (if p>=1) and p%3 (if p<=14).
// ---------------------------------------------------------------------------
__global__ void __launch_bounds__(1024) pass1_kernel(const float4* __restrict__ arr) {
    __shared__ float4 S[8][16][8];   // [p2l][p4][m4]  16 KB
    __shared__ float4 T[8][3][8];    // [p2l][j4][m4]   3 KB

    const int b   = blockIdx.z;
    const int p1  = blockIdx.y;
    const int h   = blockIdx.x;          // 0..1
    const int t   = threadIdx.x;
    const int m4  = t & 7;
    const int p4  = (t >> 3) & 15;
    const int p2l = t >> 7;              // 0..7
    const int p2  = h * 8 + p2l;

    const float4* __restrict__ src =
        arr + (size_t)(((((b * D + p1) * D + p2) * D) * D) + p4) * 8 + m4;

    float4 a0 = {0.f,0.f,0.f,0.f}, a1 = a0, a2 = a0;
#pragma unroll
    for (int p3 = 0; p3 < 16; ++p3) {
        float4 v = src[p3 * D * 8];
        if (p3 >= 1) {
            const int ja = (p3 - 1) % 3;
            if (ja == 0) ADD4(a0, v); else if (ja == 1) ADD4(a1, v); else ADD4(a2, v);
        }
        if (p3 <= 14) {
            const int jb = p3 % 3;
            if (jb == 0) ADD4(a0, v); else if (jb == 1) ADD4(a1, v); else ADD4(a2, v);
        }
    }

#pragma unroll
    for (int j3 = 0; j3 < 3; ++j3) {
        S[p2l][p4][m4] = (j3 == 0) ? a0 : ((j3 == 1) ? a1 : a2);
        __syncthreads();

        if (t < 192) {   // t = pp*24 + j4*8 + mm : reduce p4 -> j4 classes
            const int mm = t & 7;
            const int j4 = (t >> 3) % 3;
            const int pp = t / 24;
            float4 s = {0.f,0.f,0.f,0.f};
#pragma unroll
            for (int i = 0; i < 10; ++i) {
                const int p = 3 * (i >> 1) + j4 + (i & 1);
                ADD4(s, S[pp][p][mm]);
            }
            T[pp][j4][mm] = s;
        }
        __syncthreads();

        if (t < 72) {    // t = j2*24 + j4*8 + mm : reduce p2l -> j2 classes
            const int mm = t & 7;
            const int j4 = (t >> 3) % 3;
            const int j2 = t / 24;
            float4 s = {0.f,0.f,0.f,0.f};
#pragma unroll
            for (int pl = 0; pl < 8; ++pl) {
                const int pg = h * 8 + pl;
                const bool w = (pg >= 1 && (pg - 1) % 3 == j2) ||
                               (pg <= 14 && pg % 3 == j2);
                if (w) ADD4(s, T[pl][j4][mm]);
            }
            const int jj = j3 * 3 + j4;
            g_Q2[((((b * D + p1) * 2 + h) * 3 + j2) * 9 + jj) * 8 + mm] = s;
        }
        __syncthreads();
    }
}

// ---------------------------------------------------------------------------
// Pass 2: block (c, b), 128 threads.
//   E[c,m]  = sum_n Bbasis[c,n] * M[n,m]               (warp 0, shared)
//   G[c,m]  = sum over 20 (p1,h) slices of Q2          (split over 4 warps)
//   H[b,c]  = sum_m E[c,m]*G[c,m]
// Last block (threadfence counter) computes out[b,n] = K*sum_c H[b,c]*Acoeff[n,c].
// ---------------------------------------------------------------------------
__global__ void __launch_bounds__(128) pass2_kernel(const float* __restrict__ Mmat,
                                                    const float* __restrict__ Acoeff,
                                                    const float* __restrict__ Bbasis,
                                                    float* __restrict__ out) {
    __shared__ float E_s[32];
    __shared__ float part[4][32];
    __shared__ unsigned int rank_s;

    const int c  = blockIdx.x;   // 0..80
    const int b  = blockIdx.y;   // 0..3
    const int t  = threadIdx.x;
    const int lane = t & 31;
    const int wp   = t >> 5;

    const int j4 = c % 3;
    const int j3 = (c / 3) % 3;
    const int j2 = (c / 9) % 3;
    const int j1 = c / 27;
    const int jj = j3 * 3 + j4;

    if (t < 32) {
        float e = 0.f;
#pragma unroll
        for (int n = 0; n < MDIM; ++n)
            e += Bbasis[c * MDIM + n] * Mmat[n * MDIM + t];
        E_s[t] = e;
    }

    const float* __restrict__ q = (const float*)g_Q2;
    float g = 0.f;
#pragma unroll
    for (int k = wp; k < 20; k += 4) {       // k = i*2 + h, 5 loads per warp
        const int i  = k >> 1;
        const int hh = k & 1;
        const int p1 = 3 * (i >> 1) + j1 + (i & 1);
        const int base = (((b * D + p1) * 2 + hh) * 3 + j2) * 9 + jj;
        g += q[base * MDIM + lane];
    }
    part[wp][lane] = g;
    __syncthreads();

    if (wp == 0) {
        float G = part[0][lane] + part[1][lane] + part[2][lane] + part[3][lane];
        float h = E_s[lane] * G;
#pragma unroll
        for (int o = 16; o; o >>= 1)
            h += __shfl_xor_sync(0xffffffffu, h, o);
        if (lane == 0) g_H[b * LTOT + c] = h;
    }
    __syncthreads();

    // Last-block finalization (deterministic: single block reads all H).
    if (t == 0) {
        __threadfence();
        rank_s = atomicAdd(&g_count, 1u);
    }
    __syncthreads();

    if (rank_s == (unsigned)(LTOT * BSZ - 1)) {
        __threadfence();
        const float K = 1.0f / (16.0f * 50625.0f);
        const int bb = t >> 5;
        const int n  = t & 31;
        float s = 0.f;
#pragma unroll
        for (int cc = 0; cc < LTOT; ++cc)
            s += g_H[bb * LTOT + cc] * Acoeff[n * LTOT + cc];
        out[bb * MDIM + n] = s * K;
        if (t == 0) g_count = 0;   // reset for next graph replay
    }
}

extern "C" void kernel_launch(void* const* d_in, const int* in_sizes, int n_in,
                              void* d_out, int out_size) {
    const float4* arr   = (const float4*)d_in[0];  // [4,16,16,16,16,32]
    const float* Mmat   = (const float*)d_in[1];   // [32,32]
    const float* Acoeff = (const float*)d_in[2];   // [32,81]
    const float* Bbasis = (const float*)d_in[3];   // [81,32]
    float* out = (float*)d_out;                    // [4,32]

    dim3 g1(2, D, BSZ);                 // (h, p1, b) = 128 blocks
    pass1_kernel<<<g1, 1024>>>(arr);

    dim3 g2(LTOT, BSZ);                 // (c, b) = 324 blocks
    pass2_kernel<<<g2, 128>>>(Mmat, Acoeff, Bbasis, out);
}